// round 7
// baseline (speedup 1.0000x reference)
#include <cuda_runtime.h>
#include <cuda_bf16.h>

// GNNLayer: out[b,n] = relu( (sum_{e: dst[e]==n} adj[e]*w[e]*x[b,src[e]]) * x[0,n]*self_w[n] + b[n] )
// B=64, N=20000, E=1280000.
//
// Atomic-free CSR pipeline:
//  1) zero counts
//  2) transpose x [B,N] -> x_t [N,B]
//  3) histogram of dst
//  4) single-block prefix scan -> row_start, cursor
//  5) scatter packed {src, adj*w} (8B) into dst-sorted edge list
//  6) per-node register accumulation (16 lanes x float4), scale+bias+relu,
//     smem transpose, coalesced write of out [B,N]. No float atomics anywhere.

#define GNN_B 64
#define GNN_N 20000
#define GNN_E 1280000

__device__ float g_xt[GNN_N * GNN_B];     // x transposed [N, B]
__device__ int   g_counts[GNN_N];         // per-dst edge counts
__device__ int   g_row_start[GNN_N + 1];  // CSR row offsets
__device__ int   g_cursor[GNN_N];         // scatter cursors
__device__ int2  g_edges[GNN_E];          // packed {src, bits(adj*w)}, dst-sorted

// ---------------------------------------------------------------------------
// Kernel 1: zero the histogram counters.
// ---------------------------------------------------------------------------
__global__ void gnn_zero_kernel() {
    const int i = blockIdx.x * blockDim.x + threadIdx.x;
    if (i < GNN_N) g_counts[i] = 0;
}

// ---------------------------------------------------------------------------
// Kernel 2: transpose x [B,N] -> g_xt [N,B]. 32x32 tiles, block (32,8).
// ---------------------------------------------------------------------------
__global__ void gnn_transpose_kernel(const float* __restrict__ x) {
    __shared__ float tile[32][33];
    const int n0 = blockIdx.x * 32;
    const int b0 = blockIdx.y * 32;
    const int tx = threadIdx.x;
    const int ty = threadIdx.y;

    #pragma unroll
    for (int i = ty; i < 32; i += 8)
        tile[i][tx] = x[(b0 + i) * GNN_N + (n0 + tx)];
    __syncthreads();
    #pragma unroll
    for (int i = ty; i < 32; i += 8)
        g_xt[(n0 + i) * GNN_B + (b0 + tx)] = tile[tx][i];
}

// ---------------------------------------------------------------------------
// Kernel 3: histogram dst -> counts (int RED, spread over 20K addresses).
// ---------------------------------------------------------------------------
__global__ void gnn_hist_kernel(const int* __restrict__ dst, int num_edges) {
    const int e = blockIdx.x * blockDim.x + threadIdx.x;
    if (e < num_edges) atomicAdd(&g_counts[dst[e]], 1);
}

// ---------------------------------------------------------------------------
// Kernel 4: exclusive prefix scan of counts (one block, 1024 threads,
// 20 elements per thread + Hillis-Steele block scan). Writes row_start,
// cursor (=row_start), and row_start[N]=E.
// ---------------------------------------------------------------------------
__global__ void gnn_prefix_kernel() {
    __shared__ int part[1024];
    const int t = threadIdx.x;
    const int base = t * 20;

    int local[20];
    int s = 0;
    #pragma unroll
    for (int i = 0; i < 20; i++) {
        const int idx = base + i;
        const int v = (idx < GNN_N) ? g_counts[idx] : 0;
        local[i] = s;          // exclusive within this thread's chunk
        s += v;
    }
    part[t] = s;
    __syncthreads();

    // inclusive Hillis-Steele scan over the 1024 partials
    for (int off = 1; off < 1024; off <<= 1) {
        int v = 0;
        if (t >= off) v = part[t - off];
        __syncthreads();
        if (t >= off) part[t] += v;
        __syncthreads();
    }

    const int pre = (t == 0) ? 0 : part[t - 1];
    #pragma unroll
    for (int i = 0; i < 20; i++) {
        const int idx = base + i;
        if (idx < GNN_N) {
            const int rs = pre + local[i];
            g_row_start[idx] = rs;
            g_cursor[idx]    = rs;
        }
    }
    if (t == 1023) g_row_start[GNN_N] = part[1023];
}

// ---------------------------------------------------------------------------
// Kernel 5: scatter edges into dst-sorted order as packed {src, adj*w}.
// ---------------------------------------------------------------------------
__global__ void gnn_scatter_kernel(const float* __restrict__ adj,
                                   const float* __restrict__ w,
                                   const int*   __restrict__ src,
                                   const int*   __restrict__ dst,
                                   int num_edges) {
    const int e = blockIdx.x * blockDim.x + threadIdx.x;
    if (e >= num_edges) return;
    const int d = dst[e];
    const int pos = atomicAdd(&g_cursor[d], 1);
    int2 m;
    m.x = src[e];
    m.y = __float_as_int(adj[e] * w[e]);
    g_edges[pos] = m;
}

// ---------------------------------------------------------------------------
// Kernel 6: per-node accumulate + epilogue.
// Block = 512 threads = 32 nodes x 16 lanes; each lane owns a float4
// (4 batch slots). Register accumulation over the node's edge list, then
// scale/bias/relu, smem transpose, coalesced write of out [B,N].
// grid = 20000/32 = 625 blocks (exact).
// ---------------------------------------------------------------------------
__global__ __launch_bounds__(512) void gnn_accum_kernel(
        const float* __restrict__ x,        // row 0 used for self loop
        const float* __restrict__ self_w,
        const float* __restrict__ bias,
        float* __restrict__ out) {
    __shared__ float tile[GNN_B][33];       // [b][node-in-block]
    const int tid  = threadIdx.x;
    const int g    = tid >> 4;              // node within block, 0..31
    const int lane = tid & 15;              // 0..15
    const int n    = blockIdx.x * 32 + g;   // always < N

    const int start = __ldg(&g_row_start[n]);
    const int end   = __ldg(&g_row_start[n + 1]);

    float4 acc = make_float4(0.f, 0.f, 0.f, 0.f);
    int e = start;
    for (; e + 1 < end; e += 2) {
        const int2 m0 = g_edges[e];
        const int2 m1 = g_edges[e + 1];
        const float4 v0 = *reinterpret_cast<const float4*>(&g_xt[m0.x * GNN_B + lane * 4]);
        const float4 v1 = *reinterpret_cast<const float4*>(&g_xt[m1.x * GNN_B + lane * 4]);
        const float c0 = __int_as_float(m0.y);
        const float c1 = __int_as_float(m1.y);
        acc.x += c0 * v0.x;  acc.y += c0 * v0.y;
        acc.z += c0 * v0.z;  acc.w += c0 * v0.w;
        acc.x += c1 * v1.x;  acc.y += c1 * v1.y;
        acc.z += c1 * v1.z;  acc.w += c1 * v1.w;
    }
    if (e < end) {
        const int2 m0 = g_edges[e];
        const float4 v0 = *reinterpret_cast<const float4*>(&g_xt[m0.x * GNN_B + lane * 4]);
        const float c0 = __int_as_float(m0.y);
        acc.x += c0 * v0.x;  acc.y += c0 * v0.y;
        acc.z += c0 * v0.z;  acc.w += c0 * v0.w;
    }

    const float sl = __ldg(&x[n]) * __ldg(&self_w[n]);   // x[0][n] * self_w[n]
    const float bb = __ldg(&bias[n]);
    const int b0 = lane * 4;
    tile[b0 + 0][g] = fmaxf(acc.x * sl + bb, 0.f);
    tile[b0 + 1][g] = fmaxf(acc.y * sl + bb, 0.f);
    tile[b0 + 2][g] = fmaxf(acc.z * sl + bb, 0.f);
    tile[b0 + 3][g] = fmaxf(acc.w * sl + bb, 0.f);
    __syncthreads();

    // write out[b][n0+nl]: 2048 elems, 4 per thread; warps write contiguous 128B
    const int n0 = blockIdx.x * 32;
    #pragma unroll
    for (int j = 0; j < 4; j++) {
        const int idx = tid + j * 512;      // 0..2047
        const int b   = idx >> 5;
        const int nl  = idx & 31;
        out[b * GNN_N + n0 + nl] = tile[b][nl];
    }
}

extern "C" void kernel_launch(void* const* d_in, const int* in_sizes, int n_in,
                              void* d_out, int out_size) {
    const float* x      = (const float*)d_in[0];   // [B, N]
    const float* adj    = (const float*)d_in[1];   // [E]
    const float* w      = (const float*)d_in[2];   // [E]
    const float* self_w = (const float*)d_in[3];   // [N]
    const float* bias   = (const float*)d_in[4];   // [N]
    const int*   src    = (const int*)d_in[5];     // [E]
    const int*   dst    = (const int*)d_in[6];     // [E]
    float*       out    = (float*)d_out;           // [B, N]

    const int num_edges = in_sizes[1];             // E
    const int eg = (num_edges + 255) / 256;

    gnn_zero_kernel<<<(GNN_N + 255) / 256, 256>>>();
    gnn_transpose_kernel<<<dim3(GNN_N / 32, GNN_B / 32), dim3(32, 8)>>>(x);
    gnn_hist_kernel<<<eg, 256>>>(dst, num_edges);
    gnn_prefix_kernel<<<1, 1024>>>();
    gnn_scatter_kernel<<<eg, 256>>>(adj, w, src, dst, num_edges);
    gnn_accum_kernel<<<GNN_N / 32, 512>>>(x, self_w, bias, out);
}

// round 8
// speedup vs baseline: 1.2729x; 1.2729x over previous
#include <cuda_runtime.h>
#include <cuda_bf16.h>

// GNNLayer: out[b,n] = relu( (sum_{e: dst[e]==n} adj[e]*w[e]*x[b,src[e]]) * x[0,n]*self_w[n] + b[n] )
// B=64, N=20000, E=1280000.
//
// Atomic-free CSR pipeline (v2 — parallel scan, MLP-4 accumulate):
//  1) zero counts
//  2) transpose x [B,N] -> x_t [N,B]
//  3) histogram of dst
//  4) 3-phase coalesced prefix scan -> row_start, cursor
//  5) scatter packed {src, adj*w} (8B) into dst-sorted edge list (4 edges/thread)
//  6) per-node register accumulation (16 lanes x float4, unroll 4),
//     scale+bias+relu, smem transpose, coalesced write of out [B,N].

#define GNN_B 64
#define GNN_N 20000
#define GNN_E 1280000
#define SCAN_NB ((GNN_N + 255) / 256)     // 79 scan blocks

__device__ float g_xt[GNN_N * GNN_B];     // x transposed [N, B]
__device__ int   g_counts[GNN_N];         // per-dst edge counts
__device__ int   g_row_start[GNN_N + 1];  // CSR row offsets
__device__ int   g_cursor[GNN_N];         // scatter cursors
__device__ int   g_bsum[SCAN_NB];         // per-scan-block totals
__device__ int   g_boff[SCAN_NB];         // per-scan-block exclusive offsets
__device__ int2  g_edges[GNN_E];          // packed {src, bits(adj*w)}, dst-sorted

__device__ __forceinline__ int warp_incl_scan(int v) {
    #pragma unroll
    for (int o = 1; o < 32; o <<= 1) {
        const int u = __shfl_up_sync(0xFFFFFFFFu, v, o);
        if ((threadIdx.x & 31) >= o) v += u;
    }
    return v;
}

// ---------------------------------------------------------------------------
// Kernel 1: zero the histogram counters.
// ---------------------------------------------------------------------------
__global__ void gnn_zero_kernel() {
    const int i = blockIdx.x * blockDim.x + threadIdx.x;
    if (i < GNN_N) g_counts[i] = 0;
}

// ---------------------------------------------------------------------------
// Kernel 2: transpose x [B,N] -> g_xt [N,B]. 32x32 tiles, block (32,8).
// ---------------------------------------------------------------------------
__global__ void gnn_transpose_kernel(const float* __restrict__ x) {
    __shared__ float tile[32][33];
    const int n0 = blockIdx.x * 32;
    const int b0 = blockIdx.y * 32;
    const int tx = threadIdx.x;
    const int ty = threadIdx.y;

    #pragma unroll
    for (int i = ty; i < 32; i += 8)
        tile[i][tx] = x[(b0 + i) * GNN_N + (n0 + tx)];
    __syncthreads();
    #pragma unroll
    for (int i = ty; i < 32; i += 8)
        g_xt[(n0 + i) * GNN_B + (b0 + tx)] = tile[tx][i];
}

// ---------------------------------------------------------------------------
// Kernel 3: histogram dst -> counts (int RED spread over 20K addresses).
// ---------------------------------------------------------------------------
__global__ void gnn_hist_kernel(const int* __restrict__ dst, int num_edges) {
    const int e = blockIdx.x * blockDim.x + threadIdx.x;
    if (e < num_edges) atomicAdd(&g_counts[dst[e]], 1);
}

// ---------------------------------------------------------------------------
// Kernel 4a: per-block exclusive scan of counts (256/block, coalesced),
// writes block-local exclusive into row_start and block total into g_bsum.
// ---------------------------------------------------------------------------
__global__ void gnn_scan_block_kernel() {
    __shared__ int wsum[8];
    const int i = blockIdx.x * 256 + threadIdx.x;
    const int v = (i < GNN_N) ? g_counts[i] : 0;
    int incl = warp_incl_scan(v);
    const int warp = threadIdx.x >> 5;
    const int lane = threadIdx.x & 31;
    if (lane == 31) wsum[warp] = incl;
    __syncthreads();
    if (warp == 0) {
        int s = (lane < 8) ? wsum[lane] : 0;
        s = warp_incl_scan(s);
        if (lane < 8) wsum[lane] = s;
    }
    __syncthreads();
    if (warp > 0) incl += wsum[warp - 1];
    if (i < GNN_N) g_row_start[i] = incl - v;
    if (threadIdx.x == 255) g_bsum[blockIdx.x] = incl;
}

// ---------------------------------------------------------------------------
// Kernel 4b: scan the 79 block totals (1 block, 128 threads).
// Also writes row_start[N] = E.
// ---------------------------------------------------------------------------
__global__ void gnn_scan_tops_kernel() {
    __shared__ int wsum[4];
    const int t = threadIdx.x;
    const int v = (t < SCAN_NB) ? g_bsum[t] : 0;
    int incl = warp_incl_scan(v);
    const int warp = t >> 5;
    const int lane = t & 31;
    if (lane == 31) wsum[warp] = incl;
    __syncthreads();
    if (warp == 0) {
        int s = (lane < 4) ? wsum[lane] : 0;
        s = warp_incl_scan(s);
        if (lane < 4) wsum[lane] = s;
    }
    __syncthreads();
    if (warp > 0) incl += wsum[warp - 1];
    if (t < SCAN_NB) g_boff[t] = incl - v;
    if (t == 127) g_row_start[GNN_N] = wsum[3];   // grand total = E
}

// ---------------------------------------------------------------------------
// Kernel 4c: add block offsets; init cursors.
// ---------------------------------------------------------------------------
__global__ void gnn_scan_add_kernel() {
    const int i = blockIdx.x * 256 + threadIdx.x;
    if (i < GNN_N) {
        const int rs = g_row_start[i] + g_boff[blockIdx.x];
        g_row_start[i] = rs;
        g_cursor[i]    = rs;
    }
}

// ---------------------------------------------------------------------------
// Kernel 5: scatter edges into dst-sorted order as packed {src, adj*w}.
// 4 independent edges per thread (separate coalesced chunks) so the
// returning cursor atomics overlap.
// ---------------------------------------------------------------------------
__global__ void gnn_scatter_kernel(const float* __restrict__ adj,
                                   const float* __restrict__ w,
                                   const int*   __restrict__ src,
                                   const int*   __restrict__ dst,
                                   int num_edges, int chunk) {
    const int gtid = blockIdx.x * blockDim.x + threadIdx.x;
    #pragma unroll
    for (int j = 0; j < 4; j++) {
        const int e = gtid + j * chunk;
        if (e < num_edges) {
            const int d   = dst[e];
            const int pos = atomicAdd(&g_cursor[d], 1);
            int2 m;
            m.x = src[e];
            m.y = __float_as_int(adj[e] * w[e]);
            g_edges[pos] = m;
        }
    }
}

// ---------------------------------------------------------------------------
// Kernel 6: per-node accumulate + epilogue.
// Block = 512 threads = 32 nodes x 16 lanes; each lane owns a float4.
// Unroll-4 mainloop: 4 edge-meta broadcasts then 4 float4 gathers in flight.
// Epilogue: scale/bias/relu, smem transpose, coalesced write of out [B,N].
// ---------------------------------------------------------------------------
__global__ __launch_bounds__(512) void gnn_accum_kernel(
        const float* __restrict__ x,        // row 0 used for self loop
        const float* __restrict__ self_w,
        const float* __restrict__ bias,
        float* __restrict__ out) {
    __shared__ float tile[GNN_B][33];       // [b][node-in-block]
    const int tid  = threadIdx.x;
    const int g    = tid >> 4;              // node within block, 0..31
    const int lane = tid & 15;              // 0..15
    const int n    = blockIdx.x * 32 + g;   // always < N (grid exact)

    const int start = __ldg(&g_row_start[n]);
    const int end   = __ldg(&g_row_start[n + 1]);

    float4 acc = make_float4(0.f, 0.f, 0.f, 0.f);
    int e = start;
    for (; e + 3 < end; e += 4) {
        const int2 m0 = g_edges[e];
        const int2 m1 = g_edges[e + 1];
        const int2 m2 = g_edges[e + 2];
        const int2 m3 = g_edges[e + 3];
        const float4 v0 = *reinterpret_cast<const float4*>(&g_xt[m0.x * GNN_B + lane * 4]);
        const float4 v1 = *reinterpret_cast<const float4*>(&g_xt[m1.x * GNN_B + lane * 4]);
        const float4 v2 = *reinterpret_cast<const float4*>(&g_xt[m2.x * GNN_B + lane * 4]);
        const float4 v3 = *reinterpret_cast<const float4*>(&g_xt[m3.x * GNN_B + lane * 4]);
        const float c0 = __int_as_float(m0.y);
        const float c1 = __int_as_float(m1.y);
        const float c2 = __int_as_float(m2.y);
        const float c3 = __int_as_float(m3.y);
        acc.x += c0 * v0.x;  acc.y += c0 * v0.y;  acc.z += c0 * v0.z;  acc.w += c0 * v0.w;
        acc.x += c1 * v1.x;  acc.y += c1 * v1.y;  acc.z += c1 * v1.z;  acc.w += c1 * v1.w;
        acc.x += c2 * v2.x;  acc.y += c2 * v2.y;  acc.z += c2 * v2.z;  acc.w += c2 * v2.w;
        acc.x += c3 * v3.x;  acc.y += c3 * v3.y;  acc.z += c3 * v3.z;  acc.w += c3 * v3.w;
    }
    for (; e < end; e++) {
        const int2 m0 = g_edges[e];
        const float4 v0 = *reinterpret_cast<const float4*>(&g_xt[m0.x * GNN_B + lane * 4]);
        const float c0 = __int_as_float(m0.y);
        acc.x += c0 * v0.x;  acc.y += c0 * v0.y;  acc.z += c0 * v0.z;  acc.w += c0 * v0.w;
    }

    const float sl = __ldg(&x[n]) * __ldg(&self_w[n]);   // x[0][n] * self_w[n]
    const float bb = __ldg(&bias[n]);
    const int b0 = lane * 4;
    tile[b0 + 0][g] = fmaxf(acc.x * sl + bb, 0.f);
    tile[b0 + 1][g] = fmaxf(acc.y * sl + bb, 0.f);
    tile[b0 + 2][g] = fmaxf(acc.z * sl + bb, 0.f);
    tile[b0 + 3][g] = fmaxf(acc.w * sl + bb, 0.f);
    __syncthreads();

    // write out[b][n0+nl]: 2048 elems, 4 per thread; warps write contiguous 128B
    const int n0 = blockIdx.x * 32;
    #pragma unroll
    for (int j = 0; j < 4; j++) {
        const int idx = tid + j * 512;      // 0..2047
        const int b   = idx >> 5;
        const int nl  = idx & 31;
        out[b * GNN_N + n0 + nl] = tile[b][nl];
    }
}

extern "C" void kernel_launch(void* const* d_in, const int* in_sizes, int n_in,
                              void* d_out, int out_size) {
    const float* x      = (const float*)d_in[0];   // [B, N]
    const float* adj    = (const float*)d_in[1];   // [E]
    const float* w      = (const float*)d_in[2];   // [E]
    const float* self_w = (const float*)d_in[3];   // [N]
    const float* bias   = (const float*)d_in[4];   // [N]
    const int*   src    = (const int*)d_in[5];     // [E]
    const int*   dst    = (const int*)d_in[6];     // [E]
    float*       out    = (float*)d_out;           // [B, N]

    const int num_edges = in_sizes[1];             // E
    const int eg = (num_edges + 255) / 256;

    // chunked scatter: 4 edges per thread in separate coalesced chunks
    const int chunk = (num_edges + 3) / 4;
    const int sg    = (chunk + 255) / 256;

    gnn_zero_kernel<<<SCAN_NB, 256>>>();
    gnn_transpose_kernel<<<dim3(GNN_N / 32, GNN_B / 32), dim3(32, 8)>>>(x);
    gnn_hist_kernel<<<eg, 256>>>(dst, num_edges);
    gnn_scan_block_kernel<<<SCAN_NB, 256>>>();
    gnn_scan_tops_kernel<<<1, 128>>>();
    gnn_scan_add_kernel<<<SCAN_NB, 256>>>();
    gnn_scatter_kernel<<<sg, 256>>>(adj, w, src, dst, num_edges, chunk);
    gnn_accum_kernel<<<GNN_N / 32, 512>>>(x, self_w, bias, out);
}